// round 7
// baseline (speedup 1.0000x reference)
#include <cuda_runtime.h>
#include <cuda_fp16.h>
#include <cstdint>

// ---------------------------------------------------------------------------
// Problem constants
// ---------------------------------------------------------------------------
#define NROWS 2048      // x rows (M)
#define DIM   1024      // K
#define SCOLS 16384     // selected neurons (N)

// GEMM tiling: CTA 128x128, 8 warps in 2x4, warp tile 64x32.
// Fine-grained pipeline: K-chunk 32 (16KB/stage), 6 stages, prefetch dist 5.
#define TM 128
#define TN 128
#define KCH 32                      // K per smem stage (32 fp16 = 64B/row)
#define KITERS (DIM / KCH)          // 32
#define NSTAGES 6
#define PFDIST 5                    // stages in flight

#define A_BYTES (TM * 64)           // 8192
#define B_BYTES (TN * 64)           // 8192
#define STAGE_BYTES (A_BYTES + B_BYTES)       // 16384
#define SMEM_TOTAL (NSTAGES * STAGE_BYTES)    // 98304 -> 2 CTAs/SM

// ---------------------------------------------------------------------------
// Scratch (allocation-free: __device__ globals)
// ---------------------------------------------------------------------------
__device__ __align__(256) __half g_xh[(size_t)NROWS * DIM];   // 4 MiB
__device__ __align__(256) __half g_wh[(size_t)SCOLS * DIM];   // 32 MiB
__device__ __align__(256) float  g_bias[SCOLS];

// ---------------------------------------------------------------------------
// Helpers
// ---------------------------------------------------------------------------
__device__ __forceinline__ uint32_t smem_u32(const void* p) {
    uint32_t a;
    asm("{ .reg .u64 t; cvta.to.shared.u64 t, %1; cvt.u32.u64 %0, t; }"
        : "=r"(a) : "l"(p));
    return a;
}

__device__ __forceinline__ void cp16(uint32_t dst, const void* src) {
    asm volatile("cp.async.cg.shared.global [%0], [%1], 16;"
                 :: "r"(dst), "l"(src));
}

__device__ __forceinline__ void ldmatrix_x4(uint32_t* r, uint32_t addr) {
    asm volatile("ldmatrix.sync.aligned.m8n8.x4.shared.b16 {%0,%1,%2,%3}, [%4];"
                 : "=r"(r[0]), "=r"(r[1]), "=r"(r[2]), "=r"(r[3])
                 : "r"(addr));
}

__device__ __forceinline__ void mma16816(float* c, const uint32_t* a,
                                         uint32_t b0, uint32_t b1) {
    asm volatile(
        "mma.sync.aligned.m16n8k16.row.col.f32.f16.f16.f32 "
        "{%0,%1,%2,%3}, {%4,%5,%6,%7}, {%8,%9}, {%0,%1,%2,%3};"
        : "+f"(c[0]), "+f"(c[1]), "+f"(c[2]), "+f"(c[3])
        : "r"(a[0]), "r"(a[1]), "r"(a[2]), "r"(a[3]), "r"(b0), "r"(b1));
}

// 64B-row tile swizzle: 16B-chunk (0..3) ^= (row>>1)&3.
// Conflict-free for ldmatrix 8-row phases (even rows cover [0,64), odd
// rows cover [64,128) with distinct chunks) and for STS (8 thr / 128B).
__device__ __forceinline__ uint32_t swz(uint32_t row, uint32_t chunk) {
    return row * 64u + ((chunk ^ ((row >> 1) & 3u)) << 4);
}

// sample_ids dtype detection (int64 vs int32); ids < 65536 so int64 layout
// has all-odd-words zero. Reads only first 64B — safe in both layouts.
__device__ __forceinline__ long long load_id(const void* ids_raw, int s) {
    const int* i32 = (const int*)ids_raw;
    bool is64 = ((i32[1] | i32[3] | i32[5] | i32[7] |
                  i32[9] | i32[11] | i32[13] | i32[15]) == 0);
    long long id = is64 ? ((const long long*)ids_raw)[s] : (long long)i32[s];
    return id & 0xFFFFLL;   // OUT = 65536: hard OOB guard
}

// ---------------------------------------------------------------------------
// Kernel 1 (fused): blocks [0, SCOLS): gather W[sample_ids] -> g_wh (f16) and
// bias; blocks [SCOLS, SCOLS+NROWS): convert one x row f32 -> f16.
// ---------------------------------------------------------------------------
__global__ void prep_kernel(const float* __restrict__ x,
                            const float* __restrict__ w,
                            const float* __restrict__ bias,
                            const void* __restrict__ ids_raw) {
    const int b = blockIdx.x;
    const int t = threadIdx.x;              // 256 threads
    if (b < SCOLS) {
        long long id = load_id(ids_raw, b);
        const float4* src = reinterpret_cast<const float4*>(w + (size_t)id * DIM);
        __half2* dst = reinterpret_cast<__half2*>(g_wh + (size_t)b * DIM);
        float4 v = src[t];
        dst[2 * t + 0] = __floats2half2_rn(v.x, v.y);
        dst[2 * t + 1] = __floats2half2_rn(v.z, v.w);
        if (t == 0) g_bias[b] = bias[id];
    } else {
        const int row = b - SCOLS;
        const float4* src = reinterpret_cast<const float4*>(x + (size_t)row * DIM);
        __half2* dst = reinterpret_cast<__half2*>(g_xh + (size_t)row * DIM);
        float4 v = src[t];
        dst[2 * t + 0] = __floats2half2_rn(v.x, v.y);
        dst[2 * t + 1] = __floats2half2_rn(v.z, v.w);
    }
}

// ---------------------------------------------------------------------------
// Kernel 2: GEMM  out[m][n] = sum_k xh[m][k]*wh[n][k] + bias_sel[n]
// CTA 128x128, warp 64x32 (4x4 m16n8k16), 6-stage fine-grained cp.async
// pipeline (16KB stages, distance 5), 2 CTAs/SM.
// ---------------------------------------------------------------------------
__global__ void __launch_bounds__(256, 2)
gemm_kernel(float* __restrict__ out) {
    extern __shared__ char smem[];
    const uint32_t sb = smem_u32(smem);
    const int tid = threadIdx.x;
    const int wid = tid >> 5;
    const int lid = tid & 31;
    const int wm = wid >> 2;            // 0..1  (M)
    const int wn = wid & 3;             // 0..3  (N)
    const int m0 = blockIdx.x * TM;     // 16 M-blocks (x-fastest: B L2 reuse)
    const int n0 = blockIdx.y * TN;     // 128 N-blocks

    const __half* Ag = g_xh + (size_t)m0 * DIM;
    const __half* Bg = g_wh + (size_t)n0 * DIM;

    float c[4][4][4];
#pragma unroll
    for (int i = 0; i < 4; ++i)
#pragma unroll
        for (int j = 0; j < 4; ++j)
#pragma unroll
            for (int q = 0; q < 4; ++q) c[i][j][q] = 0.f;

    const int lrow = lid & 15;
    const int lsel = lid >> 4;
    const int arow = wm * 64 + lrow;    // + mt*16
    const int brow = wn * 32 + lrow;    // + nh*16

    // Per-thread load mapping: 4 x 16B chunks per stage (A:512, B:512 chunks).
    // v = tid + i*256; isB = v>>9; row = (v&511)>>2; ch = v&3.
    auto issue_stage = [&](int kb, int slot) {
        const __half* Agk = Ag + kb * KCH;
        const __half* Bgk = Bg + kb * KCH;
        const uint32_t base = sb + slot * STAGE_BYTES;
#pragma unroll
        for (int i = 0; i < 4; ++i) {
            const int v = tid + i * 256;
            const int isB = v >> 9;
            const int vv = v & 511;
            const int row = vv >> 2;
            const int ch = vv & 3;
            cp16(base + (isB ? A_BYTES : 0) + swz(row, ch),
                 (isB ? Bgk : Agk) + (size_t)row * DIM + ch * 8);
        }
        asm volatile("cp.async.commit_group;");
    };

    // ---- prologue: stages 0..4 ----
#pragma unroll
    for (int s = 0; s < PFDIST; ++s) issue_stage(s, s);

    uint32_t a0[4][4], a1[4][4], b0[2][4], b1[2][4];

#pragma unroll 1
    for (int kb = 0; kb < KITERS; ++kb) {
        asm volatile("cp.async.wait_group 4;");   // stage kb landed
        __syncthreads();  // visible to all; slot (kb+5)%6's readers done
        if (kb + PFDIST < KITERS) {
            issue_stage(kb + PFDIST, (kb + PFDIST) % NSTAGES);
        } else {
            asm volatile("cp.async.commit_group;");   // empty: keep count
        }

        const uint32_t abase = sb + (kb % NSTAGES) * STAGE_BYTES;
        const uint32_t bbase = abase + A_BYTES;

        // preload ks=0 fragments (chunks 0,1)
#pragma unroll
        for (int mt = 0; mt < 4; ++mt)
            ldmatrix_x4(a0[mt], abase + swz(arow + mt * 16, lsel));
#pragma unroll
        for (int nh = 0; nh < 2; ++nh)
            ldmatrix_x4(b0[nh], bbase + swz(brow + nh * 16, lsel));

        // ks = 0: prefetch ks=1 (chunks 2,3), issue MMAs on buffer 0
#pragma unroll
        for (int mt = 0; mt < 4; ++mt)
            ldmatrix_x4(a1[mt], abase + swz(arow + mt * 16, 2 + lsel));
#pragma unroll
        for (int nh = 0; nh < 2; ++nh)
            ldmatrix_x4(b1[nh], bbase + swz(brow + nh * 16, 2 + lsel));
#pragma unroll
        for (int mt = 0; mt < 4; ++mt)
#pragma unroll
            for (int nt = 0; nt < 4; ++nt) {
                const int nh = nt >> 1, h = nt & 1;
                mma16816(c[mt][nt], a0[mt], b0[nh][h], b0[nh][2 + h]);
            }
        // ks = 1: MMAs on buffer 1
#pragma unroll
        for (int mt = 0; mt < 4; ++mt)
#pragma unroll
            for (int nt = 0; nt < 4; ++nt) {
                const int nh = nt >> 1, h = nt & 1;
                mma16816(c[mt][nt], a1[mt], b1[nh][h], b1[nh][2 + h]);
            }
    }

    // ---- epilogue: += bias, write f32 ----
    const int g = lid >> 2, t = lid & 3;
    const int ncol = n0 + wn * 32 + t * 2;
    float2 bias2[4];
#pragma unroll
    for (int nt = 0; nt < 4; ++nt) {
        bias2[nt].x = g_bias[ncol + nt * 8];
        bias2[nt].y = g_bias[ncol + nt * 8 + 1];
    }
#pragma unroll
    for (int mt = 0; mt < 4; ++mt) {
        const int r0 = m0 + wm * 64 + mt * 16 + g;
        float* p0 = out + (size_t)r0 * SCOLS + ncol;
        float* p1 = p0 + (size_t)8 * SCOLS;
#pragma unroll
        for (int nt = 0; nt < 4; ++nt) {
            float2 v0 = {c[mt][nt][0] + bias2[nt].x, c[mt][nt][1] + bias2[nt].y};
            float2 v1 = {c[mt][nt][2] + bias2[nt].x, c[mt][nt][3] + bias2[nt].y};
            *reinterpret_cast<float2*>(p0 + nt * 8) = v0;
            *reinterpret_cast<float2*>(p1 + nt * 8) = v1;
        }
    }
}

// ---------------------------------------------------------------------------
// kernel_launch
// inputs (metadata order): x f32[2048*1024], weight f32[65536*1024],
//                          bias f32[65536], sample_ids int (32 or 64)[16384]
// output: f32[2048*16384]
// ---------------------------------------------------------------------------
extern "C" void kernel_launch(void* const* d_in, const int* in_sizes, int n_in,
                              void* d_out, int out_size) {
    const float* x = (const float*)d_in[0];
    const float* w = (const float*)d_in[1];
    const float* bias = (const float*)d_in[2];
    const void* ids = d_in[3];
    float* out = (float*)d_out;

    cudaFuncSetAttribute(gemm_kernel,
                         cudaFuncAttributeMaxDynamicSharedMemorySize, SMEM_TOTAL);

    prep_kernel<<<SCOLS + NROWS, 256>>>(x, w, bias, ids);
    dim3 grid(NROWS / TM, SCOLS / TN);      // (16, 128)
    gemm_kernel<<<grid, 256, SMEM_TOTAL>>>(out);
}

// round 8
// speedup vs baseline: 1.0897x; 1.0897x over previous
#include <cuda_runtime.h>
#include <cuda_fp16.h>
#include <cstdint>

// ---------------------------------------------------------------------------
// Problem constants
// ---------------------------------------------------------------------------
#define NROWS 2048      // x rows (M)
#define DIM   1024      // K
#define SCOLS 16384     // selected neurons (N)

// GEMM tiling: CTA 128x128, 8 warps in 2x4, warp tile 64x32, 3-stage pipeline
#define TM 128
#define TN 128
#define KCH 64                      // K per smem stage (64 fp16 = 128B/row)
#define KITERS (DIM / KCH)          // 16
#define NSTAGES 3

#define A_BYTES (TM * 128)          // 16384
#define B_BYTES (TN * 128)          // 16384
#define STAGE_BYTES (A_BYTES + B_BYTES)       // 32768
#define SMEM_TOTAL (NSTAGES * STAGE_BYTES)    // 98304 -> 2 CTAs/SM

// ---------------------------------------------------------------------------
// Scratch (allocation-free: __device__ globals)
// ---------------------------------------------------------------------------
__device__ __align__(256) __half g_xh[(size_t)NROWS * DIM];   // 4 MiB
__device__ __align__(256) __half g_wh[(size_t)SCOLS * DIM];   // 32 MiB
__device__ __align__(256) float  g_bias[SCOLS];

// ---------------------------------------------------------------------------
// Helpers
// ---------------------------------------------------------------------------
__device__ __forceinline__ uint32_t smem_u32(const void* p) {
    uint32_t a;
    asm("{ .reg .u64 t; cvta.to.shared.u64 t, %1; cvt.u32.u64 %0, t; }"
        : "=r"(a) : "l"(p));
    return a;
}

__device__ __forceinline__ void cp16(uint32_t dst, const void* src) {
    asm volatile("cp.async.cg.shared.global [%0], [%1], 16;"
                 :: "r"(dst), "l"(src));
}

__device__ __forceinline__ void ldmatrix_x4(uint32_t* r, uint32_t addr) {
    asm volatile("ldmatrix.sync.aligned.m8n8.x4.shared.b16 {%0,%1,%2,%3}, [%4];"
                 : "=r"(r[0]), "=r"(r[1]), "=r"(r[2]), "=r"(r[3])
                 : "r"(addr));
}

__device__ __forceinline__ void mma16816(float* c, const uint32_t* a,
                                         uint32_t b0, uint32_t b1) {
    asm volatile(
        "mma.sync.aligned.m16n8k16.row.col.f32.f16.f16.f32 "
        "{%0,%1,%2,%3}, {%4,%5,%6,%7}, {%8,%9}, {%0,%1,%2,%3};"
        : "+f"(c[0]), "+f"(c[1]), "+f"(c[2]), "+f"(c[3])
        : "r"(a[0]), "r"(a[1]), "r"(a[2]), "r"(a[3]), "r"(b0), "r"(b1));
}

// xor swizzle within a 128B-row tile: 16B-chunk ^= (row & 7)
__device__ __forceinline__ uint32_t swz(uint32_t row, uint32_t chunk) {
    return row * 128u + ((chunk ^ (row & 7u)) << 4);
}

// sample_ids dtype detection (int64 vs int32); ids < 65536 so int64 layout
// has all-odd-words zero. Reads only first 64B — safe in both layouts.
__device__ __forceinline__ long long load_id(const void* ids_raw, int s) {
    const int* i32 = (const int*)ids_raw;
    bool is64 = ((i32[1] | i32[3] | i32[5] | i32[7] |
                  i32[9] | i32[11] | i32[13] | i32[15]) == 0);
    long long id = is64 ? ((const long long*)ids_raw)[s] : (long long)i32[s];
    return id & 0xFFFFLL;   // OUT = 65536: hard OOB guard
}

// pack 4 f32 -> 4 f16 in one 16B word
__device__ __forceinline__ uint4 cvt4(float4 v) {
    __half2 lo = __floats2half2_rn(v.x, v.y);
    __half2 hi = __floats2half2_rn(v.z, v.w);
    uint4 r;
    r.x = *reinterpret_cast<uint32_t*>(&lo);
    r.y = *reinterpret_cast<uint32_t*>(&hi);
    r.z = 0; r.w = 0;
    return r;
}

// ---------------------------------------------------------------------------
// Kernel 1 (fused): blocks [0, SCOLS): gather W[sample_ids] -> g_wh (f16) and
// bias; blocks [SCOLS, SCOLS+NROWS): convert one x row f32 -> f16.
// 128 threads: each converts 8 floats (2 float4 -> 1 uint4 = STG.128).
// ---------------------------------------------------------------------------
__global__ void prep_kernel(const float* __restrict__ x,
                            const float* __restrict__ w,
                            const float* __restrict__ bias,
                            const void* __restrict__ ids_raw) {
    const int b = blockIdx.x;
    const int t = threadIdx.x;              // 128 threads, 8 f32 each
    const float4* src;
    uint4* dst;
    if (b < SCOLS) {
        long long id = load_id(ids_raw, b);
        src = reinterpret_cast<const float4*>(w + (size_t)id * DIM);
        dst = reinterpret_cast<uint4*>(g_wh + (size_t)b * DIM);
        if (t == 0) g_bias[b] = bias[id];
    } else {
        const int row = b - SCOLS;
        src = reinterpret_cast<const float4*>(x + (size_t)row * DIM);
        dst = reinterpret_cast<uint4*>(g_xh + (size_t)row * DIM);
    }
    float4 v0 = src[2 * t];
    float4 v1 = src[2 * t + 1];
    __half2 h0 = __floats2half2_rn(v0.x, v0.y);
    __half2 h1 = __floats2half2_rn(v0.z, v0.w);
    __half2 h2 = __floats2half2_rn(v1.x, v1.y);
    __half2 h3 = __floats2half2_rn(v1.z, v1.w);
    uint4 o;
    o.x = *reinterpret_cast<uint32_t*>(&h0);
    o.y = *reinterpret_cast<uint32_t*>(&h1);
    o.z = *reinterpret_cast<uint32_t*>(&h2);
    o.w = *reinterpret_cast<uint32_t*>(&h3);
    dst[t] = o;
}

// ---------------------------------------------------------------------------
// Kernel 2: GEMM  out[m][n] = sum_k xh[m][k]*wh[n][k] + bias_sel[n]
// CTA 128x128, warp 64x32 (4x4 m16n8k16), 3-stage cp.async, 2 CTAs/SM.
// Warp-phase-staggered k-substeps + fragment double buffering.
// ---------------------------------------------------------------------------
__global__ void __launch_bounds__(256, 2)
gemm_kernel(float* __restrict__ out) {
    extern __shared__ char smem[];
    const uint32_t sb = smem_u32(smem);
    const int tid = threadIdx.x;
    const int wid = tid >> 5;
    const int lid = tid & 31;
    const int wm = wid >> 2;            // 0..1  (M)
    const int wn = wid & 3;             // 0..3  (N)
    const int m0 = blockIdx.x * TM;     // 16 M-blocks (x-fastest: B L2 reuse)
    const int n0 = blockIdx.y * TN;     // 128 N-blocks

    // k-substep phase rotation: spreads LDSM/MMA phases across the warps of
    // each SMSP so the smem-port burst of one warp overlaps MMAs of another.
    const int ph = (wid + (wid >> 2)) & 3;

    const __half* Ag = g_xh + (size_t)m0 * DIM;
    const __half* Bg = g_wh + (size_t)n0 * DIM;

    float c[4][4][4];
#pragma unroll
    for (int i = 0; i < 4; ++i)
#pragma unroll
        for (int j = 0; j < 4; ++j)
#pragma unroll
            for (int q = 0; q < 4; ++q) c[i][j][q] = 0.f;

    const int lrow = lid & 15;
    const int lsel = lid >> 4;
    const int arow = wm * 64 + lrow;    // + mt*16
    const int brow = wn * 32 + lrow;    // + nh*16

    // Per-thread load mapping: 8 x 16B chunks per stage (A:1024, B:1024).
    auto issue_stage = [&](int kb, int slot) {
        const __half* Agk = Ag + kb * KCH;
        const __half* Bgk = Bg + kb * KCH;
        const uint32_t base = sb + slot * STAGE_BYTES;
#pragma unroll
        for (int i = 0; i < 8; ++i) {
            const int v = tid + i * 256;
            const int isB = v >> 10;
            const int vv = v & 1023;
            const int row = vv >> 3;
            const int ch = vv & 7;
            cp16(base + (isB ? A_BYTES : 0) + swz(row, ch),
                 (isB ? Bgk : Agk) + (size_t)row * DIM + ch * 8);
        }
        asm volatile("cp.async.commit_group;");
    };

    // ---- prologue: stages 0,1 ----
    issue_stage(0, 0);
    issue_stage(1, 1);

    uint32_t a0[4][4], a1[4][4], b0[2][4], b1[2][4];

#pragma unroll 1
    for (int kb = 0; kb < KITERS; ++kb) {
        asm volatile("cp.async.wait_group 1;");   // stage kb landed
        __syncthreads();  // data visible; readers of slot (kb+2)%3 are done

        const uint32_t abase = sb + (kb % NSTAGES) * STAGE_BYTES;
        const uint32_t bbase = abase + A_BYTES;

        // preload step s=0 fragments FIRST (gets MMAs going before the LSU
        // is occupied by next-stage cp.asyncs)
        {
            const int ch = (ph << 1) + lsel;   // ks = ph
#pragma unroll
            for (int mt = 0; mt < 4; ++mt)
                ldmatrix_x4(a0[mt], abase + swz(arow + mt * 16, ch));
#pragma unroll
            for (int nh = 0; nh < 2; ++nh)
                ldmatrix_x4(b0[nh], bbase + swz(brow + nh * 16, ch));
        }

        if (kb + 2 < KITERS) issue_stage(kb + 2, (kb + 2) % NSTAGES);

#pragma unroll
        for (int s = 0; s < 4; ++s) {
            uint32_t (*ac)[4] = (s & 1) ? a1 : a0;
            uint32_t (*bc)[4] = (s & 1) ? b1 : b0;
            uint32_t (*an)[4] = (s & 1) ? a0 : a1;
            uint32_t (*bn)[4] = (s & 1) ? b0 : b1;
            if (s < 3) {   // prefetch step s+1 while MMAs of s issue
                const int ks = (s + 1 + ph) & 3;
                const int ch = (ks << 1) + lsel;
#pragma unroll
                for (int mt = 0; mt < 4; ++mt)
                    ldmatrix_x4(an[mt], abase + swz(arow + mt * 16, ch));
#pragma unroll
                for (int nh = 0; nh < 2; ++nh)
                    ldmatrix_x4(bn[nh], bbase + swz(brow + nh * 16, ch));
            }
#pragma unroll
            for (int mt = 0; mt < 4; ++mt)
#pragma unroll
                for (int nt = 0; nt < 4; ++nt) {
                    const int nh = nt >> 1, h = nt & 1;
                    mma16816(c[mt][nt], ac[mt], bc[nh][h], bc[nh][2 + h]);
                }
        }
        // no trailing barrier: next iteration's __syncthreads provides the
        // read-complete guarantee before slot reuse.
    }

    // ---- epilogue: += bias, write f32 ----
    const int g = lid >> 2, t = lid & 3;
    const int ncol = n0 + wn * 32 + t * 2;
    float2 bias2[4];
#pragma unroll
    for (int nt = 0; nt < 4; ++nt) {
        bias2[nt].x = g_bias[ncol + nt * 8];
        bias2[nt].y = g_bias[ncol + nt * 8 + 1];
    }
#pragma unroll
    for (int mt = 0; mt < 4; ++mt) {
        const int r0 = m0 + wm * 64 + mt * 16 + g;
        float* p0 = out + (size_t)r0 * SCOLS + ncol;
        float* p1 = p0 + (size_t)8 * SCOLS;
#pragma unroll
        for (int nt = 0; nt < 4; ++nt) {
            float2 v0 = {c[mt][nt][0] + bias2[nt].x, c[mt][nt][1] + bias2[nt].y};
            float2 v1 = {c[mt][nt][2] + bias2[nt].x, c[mt][nt][3] + bias2[nt].y};
            *reinterpret_cast<float2*>(p0 + nt * 8) = v0;
            *reinterpret_cast<float2*>(p1 + nt * 8) = v1;
        }
    }
}

// ---------------------------------------------------------------------------
// kernel_launch
// inputs (metadata order): x f32[2048*1024], weight f32[65536*1024],
//                          bias f32[65536], sample_ids int (32 or 64)[16384]
// output: f32[2048*16384]
// ---------------------------------------------------------------------------
extern "C" void kernel_launch(void* const* d_in, const int* in_sizes, int n_in,
                              void* d_out, int out_size) {
    const float* x = (const float*)d_in[0];
    const float* w = (const float*)d_in[1];
    const float* bias = (const float*)d_in[2];
    const void* ids = d_in[3];
    float* out = (float*)d_out;

    cudaFuncSetAttribute(gemm_kernel,
                         cudaFuncAttributeMaxDynamicSharedMemorySize, SMEM_TOTAL);

    prep_kernel<<<SCOLS + NROWS, 128>>>(x, w, bias, ids);
    dim3 grid(NROWS / TM, SCOLS / TN);      // (16, 128)
    gemm_kernel<<<grid, 256, SMEM_TOTAL>>>(out);
}

// round 9
// speedup vs baseline: 1.1322x; 1.0390x over previous
#include <cuda_runtime.h>
#include <cuda_fp16.h>
#include <cstdint>

// ---------------------------------------------------------------------------
// Problem constants
// ---------------------------------------------------------------------------
#define NROWS 2048      // x rows (M)
#define DIM   1024      // K
#define SCOLS 16384     // selected neurons (N)

// GEMM tiling: CTA 128x128, 4 warps in 2x2, warp tile 64x64, 3-stage pipeline
#define TM 128
#define TN 128
#define KCH 64                      // K per smem stage (64 fp16 = 128B/row)
#define KITERS (DIM / KCH)          // 16
#define NSTAGES 3
#define NTHREADS 128

#define A_BYTES (TM * 128)          // 16384
#define B_BYTES (TN * 128)          // 16384
#define STAGE_BYTES (A_BYTES + B_BYTES)       // 32768
#define SMEM_TOTAL (NSTAGES * STAGE_BYTES)    // 98304 -> 2 CTAs/SM

// ---------------------------------------------------------------------------
// Scratch (allocation-free: __device__ globals)
// ---------------------------------------------------------------------------
__device__ __align__(256) __half g_xh[(size_t)NROWS * DIM];   // 4 MiB
__device__ __align__(256) __half g_wh[(size_t)SCOLS * DIM];   // 32 MiB
__device__ __align__(256) float  g_bias[SCOLS];

// ---------------------------------------------------------------------------
// Helpers
// ---------------------------------------------------------------------------
__device__ __forceinline__ uint32_t smem_u32(const void* p) {
    uint32_t a;
    asm("{ .reg .u64 t; cvta.to.shared.u64 t, %1; cvt.u32.u64 %0, t; }"
        : "=r"(a) : "l"(p));
    return a;
}

__device__ __forceinline__ void cp16(uint32_t dst, const void* src) {
    asm volatile("cp.async.cg.shared.global [%0], [%1], 16;"
                 :: "r"(dst), "l"(src));
}

__device__ __forceinline__ void ldmatrix_x4(uint32_t* r, uint32_t addr) {
    asm volatile("ldmatrix.sync.aligned.m8n8.x4.shared.b16 {%0,%1,%2,%3}, [%4];"
                 : "=r"(r[0]), "=r"(r[1]), "=r"(r[2]), "=r"(r[3])
                 : "r"(addr));
}

__device__ __forceinline__ void mma16816(float* c, const uint32_t* a,
                                         uint32_t b0, uint32_t b1) {
    asm volatile(
        "mma.sync.aligned.m16n8k16.row.col.f32.f16.f16.f32 "
        "{%0,%1,%2,%3}, {%4,%5,%6,%7}, {%8,%9}, {%0,%1,%2,%3};"
        : "+f"(c[0]), "+f"(c[1]), "+f"(c[2]), "+f"(c[3])
        : "r"(a[0]), "r"(a[1]), "r"(a[2]), "r"(a[3]), "r"(b0), "r"(b1));
}

// xor swizzle within a 128B-row tile: 16B-chunk ^= (row & 7)
__device__ __forceinline__ uint32_t swz(uint32_t row, uint32_t chunk) {
    return row * 128u + ((chunk ^ (row & 7u)) << 4);
}

// sample_ids dtype detection (int64 vs int32); ids < 65536 so int64 layout
// has all-odd-words zero. Reads only first 64B — safe in both layouts.
__device__ __forceinline__ long long load_id(const void* ids_raw, int s) {
    const int* i32 = (const int*)ids_raw;
    bool is64 = ((i32[1] | i32[3] | i32[5] | i32[7] |
                  i32[9] | i32[11] | i32[13] | i32[15]) == 0);
    long long id = is64 ? ((const long long*)ids_raw)[s] : (long long)i32[s];
    return id & 0xFFFFLL;   // OUT = 65536: hard OOB guard
}

// ---------------------------------------------------------------------------
// Kernel 1 (fused): blocks [0, SCOLS): gather W[sample_ids] -> g_wh (f16) and
// bias; blocks [SCOLS, SCOLS+NROWS): convert one x row f32 -> f16.
// 128 threads: each converts 8 floats (2 float4 -> 1 uint4 = STG.128).
// ---------------------------------------------------------------------------
__global__ void prep_kernel(const float* __restrict__ x,
                            const float* __restrict__ w,
                            const float* __restrict__ bias,
                            const void* __restrict__ ids_raw) {
    const int b = blockIdx.x;
    const int t = threadIdx.x;              // 128 threads, 8 f32 each
    const float4* src;
    uint4* dst;
    if (b < SCOLS) {
        long long id = load_id(ids_raw, b);
        src = reinterpret_cast<const float4*>(w + (size_t)id * DIM);
        dst = reinterpret_cast<uint4*>(g_wh + (size_t)b * DIM);
        if (t == 0) g_bias[b] = bias[id];
    } else {
        const int row = b - SCOLS;
        src = reinterpret_cast<const float4*>(x + (size_t)row * DIM);
        dst = reinterpret_cast<uint4*>(g_xh + (size_t)row * DIM);
    }
    float4 v0 = src[2 * t];
    float4 v1 = src[2 * t + 1];
    __half2 h0 = __floats2half2_rn(v0.x, v0.y);
    __half2 h1 = __floats2half2_rn(v0.z, v0.w);
    __half2 h2 = __floats2half2_rn(v1.x, v1.y);
    __half2 h3 = __floats2half2_rn(v1.z, v1.w);
    uint4 o;
    o.x = *reinterpret_cast<uint32_t*>(&h0);
    o.y = *reinterpret_cast<uint32_t*>(&h1);
    o.z = *reinterpret_cast<uint32_t*>(&h2);
    o.w = *reinterpret_cast<uint32_t*>(&h3);
    dst[t] = o;
}

// ---------------------------------------------------------------------------
// Kernel 2: GEMM  out[m][n] = sum_k xh[m][k]*wh[n][k] + bias_sel[n]
// CTA 128x128, 4 warps (2x2), warp tile 64x64 (4x8 m16n8k16),
// 3-stage cp.async pipeline, 2 CTAs/SM.
// ---------------------------------------------------------------------------
__global__ void __launch_bounds__(NTHREADS, 2)
gemm_kernel(float* __restrict__ out) {
    extern __shared__ char smem[];
    const uint32_t sb = smem_u32(smem);
    const int tid = threadIdx.x;
    const int wid = tid >> 5;
    const int lid = tid & 31;
    const int wm = wid >> 1;            // 0..1  (M)
    const int wn = wid & 1;             // 0..1  (N)
    const int m0 = blockIdx.x * TM;     // 16 M-blocks (x-fastest: B L2 reuse)
    const int n0 = blockIdx.y * TN;     // 128 N-blocks

    const __half* Ag = g_xh + (size_t)m0 * DIM;
    const __half* Bg = g_wh + (size_t)n0 * DIM;

    float c[4][8][4];
#pragma unroll
    for (int i = 0; i < 4; ++i)
#pragma unroll
        for (int j = 0; j < 8; ++j)
#pragma unroll
            for (int q = 0; q < 4; ++q) c[i][j][q] = 0.f;

    const int lrow = lid & 15;
    const int lsel = lid >> 4;
    const int arow = wm * 64 + lrow;    // + mt*16
    const int brow = wn * 64 + lrow;    // + nh*16

    // Per-thread load mapping: 16 x 16B chunks per stage (A:1024, B:1024).
    auto issue_stage = [&](int kb, int slot) {
        const __half* Agk = Ag + kb * KCH;
        const __half* Bgk = Bg + kb * KCH;
        const uint32_t base = sb + slot * STAGE_BYTES;
#pragma unroll
        for (int i = 0; i < 16; ++i) {
            const int v = tid + i * NTHREADS;
            const int isB = v >> 10;
            const int vv = v & 1023;
            const int row = vv >> 3;
            const int ch = vv & 7;
            cp16(base + (isB ? A_BYTES : 0) + swz(row, ch),
                 (isB ? Bgk : Agk) + (size_t)row * DIM + ch * 8);
        }
        asm volatile("cp.async.commit_group;");
    };

    // ---- prologue: stages 0,1 ----
    issue_stage(0, 0);
    issue_stage(1, 1);

#pragma unroll 1
    for (int kb = 0; kb < KITERS; ++kb) {
        asm volatile("cp.async.wait_group 1;");   // stage kb landed
        __syncthreads();  // data visible; readers of slot (kb+2)%3 are done
        if (kb + 2 < KITERS) issue_stage(kb + 2, (kb + 2) % NSTAGES);

        const uint32_t abase = sb + (kb % NSTAGES) * STAGE_BYTES;
        const uint32_t bbase = abase + A_BYTES;

#pragma unroll
        for (int ks = 0; ks < 4; ++ks) {
            const int ch = ks * 2 + lsel;
            uint32_t a[4][4];
#pragma unroll
            for (int mt = 0; mt < 4; ++mt)
                ldmatrix_x4(a[mt], abase + swz(arow + mt * 16, ch));
            uint32_t b[4][4];
#pragma unroll
            for (int nh = 0; nh < 4; ++nh)
                ldmatrix_x4(b[nh], bbase + swz(brow + nh * 16, ch));
#pragma unroll
            for (int mt = 0; mt < 4; ++mt)
#pragma unroll
                for (int nt = 0; nt < 8; ++nt) {
                    const int nh = nt >> 1, h = nt & 1;
                    mma16816(c[mt][nt], a[mt], b[nh][h], b[nh][2 + h]);
                }
        }
        // no trailing barrier: next iteration's __syncthreads provides the
        // read-complete guarantee before slot reuse.
    }

    // ---- epilogue: += bias, write f32 ----
    const int g = lid >> 2, t = lid & 3;
    const int ncol = n0 + wn * 64 + t * 2;
    float2 bias2[8];
#pragma unroll
    for (int nt = 0; nt < 8; ++nt) {
        bias2[nt].x = g_bias[ncol + nt * 8];
        bias2[nt].y = g_bias[ncol + nt * 8 + 1];
    }
#pragma unroll
    for (int mt = 0; mt < 4; ++mt) {
        const int r0 = m0 + wm * 64 + mt * 16 + g;
        float* p0 = out + (size_t)r0 * SCOLS + ncol;
        float* p1 = p0 + (size_t)8 * SCOLS;
#pragma unroll
        for (int nt = 0; nt < 8; ++nt) {
            float2 v0 = {c[mt][nt][0] + bias2[nt].x, c[mt][nt][1] + bias2[nt].y};
            float2 v1 = {c[mt][nt][2] + bias2[nt].x, c[mt][nt][3] + bias2[nt].y};
            *reinterpret_cast<float2*>(p0 + nt * 8) = v0;
            *reinterpret_cast<float2*>(p1 + nt * 8) = v1;
        }
    }
}

// ---------------------------------------------------------------------------
// kernel_launch
// inputs (metadata order): x f32[2048*1024], weight f32[65536*1024],
//                          bias f32[65536], sample_ids int (32 or 64)[16384]
// output: f32[2048*16384]
// ---------------------------------------------------------------------------
extern "C" void kernel_launch(void* const* d_in, const int* in_sizes, int n_in,
                              void* d_out, int out_size) {
    const float* x = (const float*)d_in[0];
    const float* w = (const float*)d_in[1];
    const float* bias = (const float*)d_in[2];
    const void* ids = d_in[3];
    float* out = (float*)d_out;

    cudaFuncSetAttribute(gemm_kernel,
                         cudaFuncAttributeMaxDynamicSharedMemorySize, SMEM_TOTAL);

    prep_kernel<<<SCOLS + NROWS, 128>>>(x, w, bias, ids);
    dim3 grid(NROWS / TM, SCOLS / TN);      // (16, 128)
    gemm_kernel<<<grid, NTHREADS, SMEM_TOTAL>>>(out);
}